// round 16
// baseline (speedup 1.0000x reference)
#include <cuda_runtime.h>
#include <cuda_fp16.h>
#include <math.h>

#define BB 2
#define TT 2048
#define DD 512
#define HH 8
#define DH 64
#define MT (BB*TT)   // 4096
#define NC 32
#define CS 64

// ---- scratch (static device globals; no allocation) ----
__device__ __half g_Xh[MT*DD];
__device__ __half g_W5h[5*DD*DD];
__device__ __half g_Yh[MT*DD];
__device__ __half g_Qh[MT*DD];
__device__ __half g_Kh[MT*DD];
__device__ __half g_Vh[MT*DD];
__device__ __half g_Gh[MT*DD];
__device__ __half g_S[BB*HH*NC*DH*DH];
__device__ float  g_P[BB*HH*4*DH*DH];     // per-segment sums

// ---- helpers ----
__device__ __forceinline__ void mma16(float* c, const unsigned* a, const unsigned* b) {
    asm volatile("mma.sync.aligned.m16n8k16.row.col.f32.f16.f16.f32 "
        "{%0,%1,%2,%3}, {%4,%5,%6,%7}, {%8,%9}, {%0,%1,%2,%3};\n"
        : "+f"(c[0]), "+f"(c[1]), "+f"(c[2]), "+f"(c[3])
        : "r"(a[0]), "r"(a[1]), "r"(a[2]), "r"(a[3]), "r"(b[0]), "r"(b[1]));
}
__device__ __forceinline__ void ldm4(unsigned* r, unsigned addr) {
    asm volatile("ldmatrix.sync.aligned.m8n8.x4.shared.b16 {%0,%1,%2,%3}, [%4];"
        : "=r"(r[0]), "=r"(r[1]), "=r"(r[2]), "=r"(r[3]) : "r"(addr));
}
__device__ __forceinline__ void ldm4t(unsigned* r, unsigned addr) {
    asm volatile("ldmatrix.sync.aligned.m8n8.x4.trans.shared.b16 {%0,%1,%2,%3}, [%4];"
        : "=r"(r[0]), "=r"(r[1]), "=r"(r[2]), "=r"(r[3]) : "r"(addr));
}
__device__ __forceinline__ void cp16h(__half* smem, const __half* g) {
    unsigned s = (unsigned)__cvta_generic_to_shared(smem);
    asm volatile("cp.async.cg.shared.global [%0], [%1], 16;\n" :: "r"(s), "l"(g));
}
#define CP_COMMIT() asm volatile("cp.async.commit_group;\n" ::: "memory")
#define CP_WAIT1()  asm volatile("cp.async.wait_group 1;\n" ::: "memory")

// ============================================================
// fp16 pre-conversion: flat grid over x + 5 weights.
// ============================================================
__global__ __launch_bounds__(256) void conv_half(
    const float* __restrict__ x,
    const float* __restrict__ w0, const float* __restrict__ w1,
    const float* __restrict__ w2, const float* __restrict__ w3,
    const float* __restrict__ w4,
    __half* __restrict__ xo, __half* __restrict__ wo)
{
    int i = blockIdx.x * 256 + threadIdx.x;
    const float4* src;
    __half2* dst;
    int idx;
    if (i < 524288) {
        src = (const float4*)x; dst = (__half2*)xo; idx = i;
    } else {
        int j = i - 524288;
        int z = j >> 16;
        idx = j & 65535;
        const float* s = (z==0)?w0:(z==1)?w1:(z==2)?w2:(z==3)?w3:w4;
        src = (const float4*)s;
        dst = (__half2*)(wo + (size_t)z * DD * DD);
    }
    float4 v = src[idx];
    dst[2*idx]   = __floats2half2_rn(v.x, v.y);
    dst[2*idx+1] = __floats2half2_rn(v.z, v.w);
}

// ============================================================
// fp16 GEMM body (template <MTILES, BK>), 4 warps, 3-stage cp.async.
// ============================================================
#define SM4 (3*(128*72 + 64*136)*2)   // MTILES=4, BK=64: 107520
#define SM2 (3*(64*40 + 32*136)*2)    // MTILES=2, BK=32: 41472

template<int MTILES, int BK>
__device__ __forceinline__ void gemm_body_h(const __half* __restrict__ A,
                                            const __half* __restrict__ B,
                                            float* __restrict__ Cf,
                                            __half* __restrict__ Ch,
                                            float alpha)
{
    constexpr int BM = MTILES * 32;
    constexpr int APAD = BK + 8;
    constexpr int HASz = BM * APAD;
    constexpr int HBSz = BK * 136;
    constexpr int NTILE = DD / BK;
    constexpr int TPR = 128 / BK;
    constexpr int ACP = BM * BK / 1024;
    constexpr int SEGS = BK / 8;

    extern __shared__ __half smh[];
    __half* Asm = smh;
    __half* Bsm = smh + 3*HASz;

    int tid = threadIdx.x;
    int w = tid >> 5, lane = tid & 31;
    int g = lane >> 2, t = lane & 3;
    int wm = (w >> 1) * (MTILES * 16);
    int wn = (w & 1) * 64;
    int bm = blockIdx.y * BM, bn = blockIdx.x * 128;

    int bkr = tid / TPR, bq = (tid % TPR) * (128 / TPR);
    const __half* Bg = B + (size_t)bkr * DD + bn + bq;

    float acc[MTILES][8][4];
    #pragma unroll
    for (int i = 0; i < MTILES; i++)
        #pragma unroll
        for (int j = 0; j < 8; j++)
            #pragma unroll
            for (int q = 0; q < 4; q++) acc[i][j][q] = 0.f;

    auto load_chunk = [&](int kt, int s) {
        int off = kt * BK;
        #pragma unroll
        for (int i = 0; i < ACP; i++) {
            int o = i * 128 + tid;
            int row = o / SEGS, sg = (o % SEGS) * 8;
            cp16h(&Asm[s*HASz + row*APAD + sg],
                  A + (size_t)(bm + row) * DD + off + sg);
        }
        #pragma unroll
        for (int i = 0; i < BK/8; i++)
            cp16h(&Bsm[s*HBSz + bkr*136 + bq + 8*i], Bg + (size_t)off * DD + 8*i);
    };

    load_chunk(0, 0); CP_COMMIT();
    load_chunk(1, 1); CP_COMMIT();

    int lrow = lane & 15, lcol = (lane >> 4) << 3;

    #pragma unroll 1
    for (int kt = 0; kt < NTILE; kt++) {
        int cur = kt % 3;
        CP_WAIT1();
        __syncthreads();

        if (kt + 2 < NTILE)
            load_chunk(kt + 2, (kt + 2) % 3);
        CP_COMMIT();

        unsigned abase = (unsigned)__cvta_generic_to_shared(Asm + cur*HASz)
                       + ((wm + lrow) * APAD + lcol) * 2;
        unsigned bbase = (unsigned)__cvta_generic_to_shared(Bsm + cur*HBSz)
                       + (lrow * 136 + wn + lcol) * 2;

        #pragma unroll
        for (int ks = 0; ks < BK/16; ks++) {
            int k0 = ks * 16;
            unsigned a[MTILES][4], bf[4][4];
            #pragma unroll
            for (int mt = 0; mt < MTILES; mt++)
                ldm4(a[mt], abase + (mt*16*APAD + k0) * 2);
            #pragma unroll
            for (int n2 = 0; n2 < 4; n2++)
                ldm4t(bf[n2], bbase + (k0*136 + n2*16) * 2);
            #pragma unroll
            for (int mt = 0; mt < MTILES; mt++)
                #pragma unroll
                for (int nt = 0; nt < 8; nt++)
                    mma16(acc[mt][nt], a[mt], &bf[nt >> 1][(nt & 1) * 2]);
        }
    }

    #pragma unroll
    for (int mt = 0; mt < MTILES; mt++)
        #pragma unroll
        for (int nt = 0; nt < 8; nt++) {
            int r = bm + wm + mt * 16 + g;
            int c = bn + wn + nt * 8 + 2 * t;
            if (Ch) {
                ((__half2*)&Ch[(size_t)r * DD + c])[0] =
                    __floats2half2_rn(alpha * acc[mt][nt][0], alpha * acc[mt][nt][1]);
                ((__half2*)&Ch[(size_t)(r + 8) * DD + c])[0] =
                    __floats2half2_rn(alpha * acc[mt][nt][2], alpha * acc[mt][nt][3]);
            } else {
                *(float2*)&Cf[(size_t)r * DD + c] =
                    make_float2(alpha * acc[mt][nt][0], alpha * acc[mt][nt][1]);
                *(float2*)&Cf[(size_t)(r + 8) * DD + c] =
                    make_float2(alpha * acc[mt][nt][2], alpha * acc[mt][nt][3]);
            }
        }
}

__global__ __launch_bounds__(128, 2) void proj_kv(const __half* __restrict__ x,
    const __half* __restrict__ W, __half* Ko, __half* Vo)
{
    const __half* Bp; __half* Cph;
    if (blockIdx.z == 0) { Bp = W + DD*DD;   Cph = Ko; }
    else                 { Bp = W + 2*DD*DD; Cph = Vo; }
    gemm_body_h<4, 64>(x, Bp, nullptr, Cph, 1.f);
}

__global__ __launch_bounds__(128, 2) void proj_qg(const __half* __restrict__ x,
    const __half* __restrict__ W, __half* Qo, __half* Go)
{
    const __half* Bp; __half* Cph; float alpha;
    if (blockIdx.z == 0) { Bp = W;           Cph = Qo; alpha = 0.125f; }
    else                 { Bp = W + 3*DD*DD; Cph = Go; alpha = 1.f; }
    gemm_body_h<4, 64>(x, Bp, nullptr, Cph, alpha);
}

__global__ __launch_bounds__(128, 4) void gemm_out(const __half* __restrict__ A,
                                                   const __half* __restrict__ B,
                                                   float* __restrict__ C)
{
    gemm_body_h<2, 32>(A, B, C, nullptr, 1.f);
}

// ============================================================
// Fused chunk outer-product + segment-local scan.
// Grid (seg=4, H, B). Each block walks its 8 chunks, keeps the
// running decayed 64x64 state in MMA accumulator registers,
// writes exclusive prefixes S_local (fp16) + segment sum P (fp32).
// ============================================================
#define TST 72

__global__ __launch_bounds__(256) void chunk_scan(const __half* __restrict__ K,
                                                  const __half* __restrict__ V,
                                                  __half* __restrict__ S,
                                                  float* __restrict__ P)
{
    __shared__ __align__(16) __half Ksm[64*TST];
    __shared__ __align__(16) __half Vd[64*TST];

    int seg = blockIdx.x, h = blockIdx.y, b = blockIdx.z;
    int tid = threadIdx.x;
    int w = tid >> 5, lane = tid & 31;
    int g = lane >> 2, t = lane & 3;
    int wi = (w >> 2) * 32, wj = (w & 3) * 16;

    float log2g = log2f(1.f - exp2f(-5.f - (float)h));
    float gc = exp2f(64.f * log2g);          // gamma^64 (chunk decay)

    int lr = tid >> 2, lc8 = (tid & 3) * 16;
    __half2 dec2 = __float2half2_rn(exp2f(log2g * (float)(CS - lr)));

    const __half* Kb = K + ((size_t)b * TT + (size_t)(seg * 8) * CS + lr) * DD + h * DH + lc8;
    const __half* Vb = V + ((size_t)b * TT + (size_t)(seg * 8) * CS + lr) * DD + h * DH + lc8;

    // prefetch chunk 0 of this segment
    float4 kr0 = *(const float4*)Kb;
    float4 kr1 = *(const float4*)(Kb + 8);
    float4 vr0 = *(const float4*)Vb;
    float4 vr1 = *(const float4*)(Vb + 8);

    float st[2][2][4];
    #pragma unroll
    for (int i = 0; i < 2; i++)
        #pragma unroll
        for (int j = 0; j < 2; j++)
            #pragma unroll
            for (int q = 0; q < 4; q++) st[i][j][q] = 0.f;

    unsigned kbase = (unsigned)__cvta_generic_to_shared(Ksm);
    unsigned vbase = (unsigned)__cvta_generic_to_shared(Vd);
    int lrow = lane & 15, lcol = (lane >> 4) << 3;
    int jrow = (lane & 7) | ((lane >> 4) << 3);
    int dcol = ((lane >> 3) & 1) << 3;

    size_t sstep = (size_t)CS * DD;   // halves per chunk

    #pragma unroll 1
    for (int j = 0; j < 8; j++) {
        // store current chunk to smem (decay on V)
        *(float4*)&Ksm[lr*TST + lc8]     = kr0;
        *(float4*)&Ksm[lr*TST + lc8 + 8] = kr1;
        {
            __half2 vv[8];
            *(float4*)&vv[0] = vr0;
            *(float4*)&vv[4] = vr1;
            #pragma unroll
            for (int u = 0; u < 8; u++)
                *(__half2*)&Vd[lr*TST + lc8 + 2*u] = __hmul2(vv[u], dec2);
        }
        __syncthreads();

        // prefetch next chunk
        if (j < 7) {
            kr0 = *(const float4*)(Kb + (size_t)(j+1) * sstep);
            kr1 = *(const float4*)(Kb + (size_t)(j+1) * sstep + 8);
            vr0 = *(const float4*)(Vb + (size_t)(j+1) * sstep);
            vr1 = *(const float4*)(Vb + (size_t)(j+1) * sstep + 8);
        }

        // B_c = K^T (decayed V)
        float bacc[2][2][4];
        #pragma unroll
        for (int i = 0; i < 2; i++)
            #pragma unroll
            for (int jj = 0; jj < 2; jj++)
                #pragma unroll
                for (int q = 0; q < 4; q++) bacc[i][jj][q] = 0.f;

        #pragma unroll
        for (int ks = 0; ks < 4; ks++) {
            int j0 = ks * 16;
            unsigned a[2][4], bv[4];
            #pragma unroll
            for (int mt = 0; mt < 2; mt++)
                ldm4t(a[mt], kbase + ((j0 + jrow)*TST + wi + mt*16 + dcol) * 2);
            ldm4t(bv, vbase + ((j0 + lrow)*TST + wj + lcol) * 2);
            #pragma unroll
            for (int mt = 0; mt < 2; mt++)
                #pragma unroll
                for (int nt = 0; nt < 2; nt++)
                    mma16(bacc[mt][nt], a[mt], &bv[2*nt]);
        }

        // write exclusive prefix (state before this chunk), then update
        int c = seg * 8 + j;
        __half* Sb = S + (((size_t)(b * HH + h)) * NC + c) * (DH * DH);
        #pragma unroll
        for (int mt = 0; mt < 2; mt++)
            #pragma unroll
            for (int nt = 0; nt < 2; nt++) {
                int r = wi + mt * 16 + g;
                int cc = wj + nt * 8 + 2 * t;
                *(__half2*)&Sb[r * DH + cc] =
                    __floats2half2_rn(st[mt][nt][0], st[mt][nt][1]);
                *(__half2*)&Sb[(r + 8) * DH + cc] =
                    __floats2half2_rn(st[mt][nt][2], st[mt][nt][3]);
                #pragma unroll
                for (int q = 0; q < 4; q++)
                    st[mt][nt][q] = gc * st[mt][nt][q] + bacc[mt][nt][q];
            }
        __syncthreads();
    }

    // segment sum (fp32)
    float* Pb = P + (((size_t)(b * HH + h)) * 4 + seg) * (DH * DH);
    #pragma unroll
    for (int mt = 0; mt < 2; mt++)
        #pragma unroll
        for (int nt = 0; nt < 2; nt++) {
            int r = wi + mt * 16 + g;
            int cc = wj + nt * 8 + 2 * t;
            *(float2*)&Pb[r * DH + cc] = make_float2(st[mt][nt][0], st[mt][nt][1]);
            *(float2*)&Pb[(r + 8) * DH + cc] = make_float2(st[mt][nt][2], st[mt][nt][3]);
        }
}

// Apply cross-segment offsets: chunks 8..31 get += gamma^(64*j) * off_seg.
// Grid (BB*HH, 24), 256 threads, 8 half2 elements per thread.
__global__ __launch_bounds__(256) void apply_offset(const float* __restrict__ P,
                                                    __half2* __restrict__ S)
{
    int bh = blockIdx.x;
    int c  = 8 + blockIdx.y;
    int seg = c >> 3, j = c & 7;
    int h = bh & 7;
    float log2g = log2f(1.f - exp2f(-5.f - (float)h));
    float gc  = exp2f(64.f * log2g);
    float gc8 = exp2f(512.f * log2g);
    float fac = exp2f(64.f * log2g * (float)j);

    const float2* Pb = (const float2*)(P + (size_t)bh * 4 * (DH * DH));
    __half2* Sb = S + ((size_t)bh * NC + c) * 2048;

    #pragma unroll
    for (int k = 0; k < 8; k++) {
        int e = threadIdx.x + k * 256;      // half2 index 0..2047
        float2 off = make_float2(0.f, 0.f);
        #pragma unroll
        for (int sp = 0; sp < 3; sp++)
            if (sp < seg) {
                float2 q = Pb[sp * 2048 + e];
                off.x = gc8 * off.x + q.x;
                off.y = gc8 * off.y + q.y;
            }
        float2 sv = __half22float2(Sb[e]);
        Sb[e] = __floats2half2_rn(sv.x + fac * off.x, sv.y + fac * off.y);
    }
    (void)gc;
}

// ============================================================
// intra + inter + GroupNorm + SiLU gate, fp16 mma
// ============================================================
__global__ __launch_bounds__(256) void retention_chunk(
    const __half* __restrict__ Q, const __half* __restrict__ K,
    const __half* __restrict__ V, const __half* __restrict__ Sm,
    const __half* __restrict__ G, const float* __restrict__ gnw,
    const float* __restrict__ gnb, __half* __restrict__ Y)
{
    __shared__ __align__(16) char smb[46608];
    __half* Qh = (__half*)smb;
    __half* Kh = (__half*)(smb + 9216);
    __half* Vh = (__half*)(smb + 18432);
    __half* Th = (__half*)(smb + 27648);
    __half* Sh = (__half*)(smb + 36864);
    float* gp  = (float*)(smb + 46080);
    float* gn_ = (float*)(smb + 46340);
    float* Os  = (float*)smb;

    int c = blockIdx.x, h = blockIdx.y, b = blockIdx.z;
    int tid = threadIdx.x;
    int w = tid >> 5, lane = tid & 31;
    int g = lane >> 2, t = lane & 3;
    int wi = (w >> 2) * 32, wj = (w & 3) * 16;

    float log2g = log2f(1.f - exp2f(-5.f - (float)h));
    if (tid < 65) gp[tid] = exp2f(log2g * (float)tid);
    if (tid < 64) gn_[tid] = exp2f(log2g * (float)(tid - 64));

    int lr = tid >> 2, lc8 = (tid & 3) * 16;
    size_t rowbase = ((size_t)b * TT + (size_t)c * CS + lr) * DD + h * DH;
    const __half* Qb = Q + rowbase;
    const __half* Kb = K + rowbase;
    const __half* Vb = V + rowbase;
    const __half* Tb = Sm + (((size_t)(b * HH + h)) * NC + c) * (DH * DH);
    __half2 dec2 = __float2half2_rn(exp2f(log2g * (float)(CS - lr)));

    *(float4*)&Qh[lr*TST + lc8]     = *(const float4*)&Qb[lc8];
    *(float4*)&Qh[lr*TST + lc8 + 8] = *(const float4*)&Qb[lc8 + 8];
    *(float4*)&Kh[lr*TST + lc8]     = *(const float4*)&Kb[lc8];
    *(float4*)&Kh[lr*TST + lc8 + 8] = *(const float4*)&Kb[lc8 + 8];
    #pragma unroll
    for (int u = 0; u < 8; u++) {
        __half2 v = *(const __half2*)&Vb[lc8 + 2*u];
        *(__half2*)&Vh[lr*TST + lc8 + 2*u] = __hmul2(v, dec2);
    }
    *(float4*)&Th[lr*TST + lc8]     = *(const float4*)&Tb[lr * DH + lc8];
    *(float4*)&Th[lr*TST + lc8 + 8] = *(const float4*)&Tb[lr * DH + lc8 + 8];
    __syncthreads();

    unsigned qbase = (unsigned)__cvta_generic_to_shared(Qh);
    unsigned kbase = (unsigned)__cvta_generic_to_shared(Kh);
    unsigned vbase = (unsigned)__cvta_generic_to_shared(Vh);
    unsigned tbase = (unsigned)__cvta_generic_to_shared(Th);
    unsigned sbase2 = (unsigned)__cvta_generic_to_shared(Sh);
    int lrow = lane & 15, lcol = (lane >> 4) << 3;
    int nrow = (lane & 7) | ((lane >> 4) << 3);
    int kc = ((lane >> 3) & 1) << 3;

    float sacc[2][2][4], iacc[2][2][4];
    #pragma unroll
    for (int i = 0; i < 2; i++)
        #pragma unroll
        for (int j = 0; j < 2; j++)
            #pragma unroll
            for (int q = 0; q < 4; q++) { sacc[i][j][q] = 0.f; iacc[i][j][q] = 0.f; }

    #pragma unroll
    for (int ks = 0; ks < 4; ks++) {
        int k0 = ks * 16;
        unsigned a[2][4], bk[4], bt[4];
        #pragma unroll
        for (int mt = 0; mt < 2; mt++)
            ldm4(a[mt], qbase + ((wi + mt*16 + lrow)*TST + k0 + lcol) * 2);
        ldm4(bk, kbase + ((wj + nrow)*TST + k0 + kc) * 2);
        ldm4t(bt, tbase + ((k0 + lrow)*TST + wj + lcol) * 2);
        #pragma unroll
        for (int mt = 0; mt < 2; mt++)
            #pragma unroll
            for (int nt = 0; nt < 2; nt++) {
                mma16(sacc[mt][nt], a[mt], &bk[2*nt]);
                mma16(iacc[mt][nt], a[mt], &bt[2*nt]);
            }
    }

    #pragma unroll
    for (int mt = 0; mt < 2; mt++) {
        #pragma unroll
        for (int nt = 0; nt < 2; nt++) {
            int r0 = wi + mt * 16 + g;
            int c0 = wj + nt * 8 + 2 * t;
            float w0 = gn_[r0], w1 = gn_[r0 + 8];
            float m00 = (r0 >= c0) ? w0 : 0.f;
            float m01 = (r0 >= c0 + 1) ? w0 : 0.f;
            float m10 = (r0 + 8 >= c0) ? w1 : 0.f;
            float m11 = (r0 + 8 >= c0 + 1) ? w1 : 0.f;
            *(__half2*)&Sh[r0*TST + c0] =
                __floats2half2_rn(sacc[mt][nt][0]*m00, sacc[mt][nt][1]*m01);
            *(__half2*)&Sh[(r0+8)*TST + c0] =
                __floats2half2_rn(sacc[mt][nt][2]*m10, sacc[mt][nt][3]*m11);
        }
    }
    __syncthreads();

    float oacc[2][2][4];
    #pragma unroll
    for (int i = 0; i < 2; i++)
        #pragma unroll
        for (int j = 0; j < 2; j++)
            #pragma unroll
            for (int q = 0; q < 4; q++) oacc[i][j][q] = 0.f;

    #pragma unroll
    for (int ks = 0; ks < 4; ks++) {
        int k0 = ks * 16;
        unsigned a[2][4], bv[4];
        #pragma unroll
        for (int mt = 0; mt < 2; mt++)
            ldm4(a[mt], sbase2 + ((wi + mt*16 + lrow)*TST + k0 + lcol) * 2);
        ldm4t(bv, vbase + ((k0 + lrow)*TST + wj + lcol) * 2);
        #pragma unroll
        for (int mt = 0; mt < 2; mt++)
            #pragma unroll
            for (int nt = 0; nt < 2; nt++)
                mma16(oacc[mt][nt], a[mt], &bv[2*nt]);
    }

    #pragma unroll
    for (int mt = 0; mt < 2; mt++) {
        #pragma unroll
        for (int nt = 0; nt < 2; nt++) {
            int r0 = wi + mt * 16 + g;
            int c0 = wj + nt * 8 + 2 * t;
            float scA = gp[r0], scB = gp[r0 + 8];
            *(float2*)&Os[r0*68 + c0] = make_float2(
                oacc[mt][nt][0] + scA * iacc[mt][nt][0],
                oacc[mt][nt][1] + scA * iacc[mt][nt][1]);
            *(float2*)&Os[(r0+8)*68 + c0] = make_float2(
                oacc[mt][nt][2] + scB * iacc[mt][nt][2],
                oacc[mt][nt][3] + scB * iacc[mt][nt][3]);
        }
    }
    __syncthreads();

    int tok = tid >> 2, sub = tid & 3;
    float vals[16];
    float s = 0.f, sq = 0.f;
    #pragma unroll
    for (int u = 0; u < 16; u++) {
        float v = Os[tok * 68 + sub * 16 + u];
        vals[u] = v; s += v; sq += v * v;
    }
    s  += __shfl_xor_sync(0xffffffffu, s, 1);
    s  += __shfl_xor_sync(0xffffffffu, s, 2);
    sq += __shfl_xor_sync(0xffffffffu, sq, 1);
    sq += __shfl_xor_sync(0xffffffffu, sq, 2);
    float mean = s * (1.f / 64.f);
    float inv = rsqrtf(sq * (1.f / 64.f) - mean * mean + 1e-5f);

    size_t row = (size_t)b * TT + (size_t)c * CS + tok;
    int wcol = h * DH + sub * 16;
    const __half2* gh = (const __half2*)(G + row * DD + wcol);
    __half2* yp = (__half2*)(Y + row * DD + wcol);
    #pragma unroll
    for (int u4 = 0; u4 < 4; u4++) {
        float4 wv = *(const float4*)&gnw[wcol + u4 * 4];
        float4 bv = *(const float4*)&gnb[wcol + u4 * 4];
        float2 g0 = __half22float2(gh[u4*2]);
        float2 g1 = __half22float2(gh[u4*2+1]);
        float z0, z1, z2, z3;
        z0 = g0.x + (vals[u4*4+0] - mean) * inv * wv.x + bv.x; z0 = z0 / (1.f + expf(-z0));
        z1 = g0.y + (vals[u4*4+1] - mean) * inv * wv.y + bv.y; z1 = z1 / (1.f + expf(-z1));
        z2 = g1.x + (vals[u4*4+2] - mean) * inv * wv.z + bv.z; z2 = z2 / (1.f + expf(-z2));
        z3 = g1.y + (vals[u4*4+3] - mean) * inv * wv.w + bv.w; z3 = z3 / (1.f + expf(-z3));
        yp[u4*2]   = __floats2half2_rn(z0, z1);
        yp[u4*2+1] = __floats2half2_rn(z2, z3);
    }
}

// ============================================================
extern "C" void kernel_launch(void* const* d_in, const int* in_sizes, int n_in,
                              void* d_out, int out_size) {
    const float* x   = (const float*)d_in[0];
    const float* WQ  = (const float*)d_in[1];
    const float* WK  = (const float*)d_in[2];
    const float* WV  = (const float*)d_in[3];
    const float* WG  = (const float*)d_in[4];
    const float* WO  = (const float*)d_in[5];
    const float* gnw = (const float*)d_in[6];
    const float* gnb = (const float*)d_in[7];
    float* out = (float*)d_out;

    __half *Xh, *Wh, *Yh, *Qh, *Kh, *Vh, *Gh, *Sp;
    float *Pp;
    cudaGetSymbolAddress((void**)&Xh, g_Xh);
    cudaGetSymbolAddress((void**)&Wh, g_W5h);
    cudaGetSymbolAddress((void**)&Yh, g_Yh);
    cudaGetSymbolAddress((void**)&Qh, g_Qh);
    cudaGetSymbolAddress((void**)&Kh, g_Kh);
    cudaGetSymbolAddress((void**)&Vh, g_Vh);
    cudaGetSymbolAddress((void**)&Gh, g_Gh);
    cudaGetSymbolAddress((void**)&Sp, g_S);
    cudaGetSymbolAddress((void**)&Pp, g_P);

    static cudaStream_t s1 = nullptr;
    static cudaEvent_t evFork = nullptr, evJoin = nullptr;
    if (!s1) {
        cudaStreamCreateWithFlags(&s1, cudaStreamNonBlocking);
        cudaEventCreateWithFlags(&evFork, cudaEventDisableTiming);
        cudaEventCreateWithFlags(&evJoin, cudaEventDisableTiming);
        cudaFuncSetAttribute(proj_kv,
                             cudaFuncAttributeMaxDynamicSharedMemorySize, SM4);
        cudaFuncSetAttribute(proj_qg,
                             cudaFuncAttributeMaxDynamicSharedMemorySize, SM4);
        cudaFuncSetAttribute(gemm_out,
                             cudaFuncAttributeMaxDynamicSharedMemorySize, SM2);
    }

    conv_half<<<3328, 256>>>(x, WQ, WK, WV, WG, WO, Xh, Wh);

    // fork: Q/G projection on side stream
    cudaEventRecord(evFork, 0);
    cudaStreamWaitEvent(s1, evFork, 0);
    proj_qg<<<dim3(DD / 128, MT / 128, 2), 128, SM4, s1>>>(Xh, Wh, Qh, Gh);

    // main stream: K/V projection -> fused chunk+scan -> offsets
    proj_kv<<<dim3(DD / 128, MT / 128, 2), 128, SM4>>>(Xh, Wh, Kh, Vh);
    chunk_scan<<<dim3(4, HH, BB), 256>>>(Kh, Vh, Sp, Pp);
    apply_offset<<<dim3(BB * HH, 24), 256>>>(Pp, (__half2*)Sp);

    // join: retention needs Q, G from s1
    cudaEventRecord(evJoin, s1);
    cudaStreamWaitEvent(0, evJoin, 0);

    retention_chunk<<<dim3(NC, HH, BB), 256>>>(Qh, Kh, Vh, Sp,
                                               Gh, gnw, gnb, Yh);

    gemm_out<<<dim3(DD / 128, MT / 64), 128, SM2>>>(
        Yh, Wh + 4 * DD * DD, out);
}

// round 17
// speedup vs baseline: 1.1340x; 1.1340x over previous
#include <cuda_runtime.h>
#include <cuda_fp16.h>
#include <math.h>

#define BB 2
#define TT 2048
#define DD 512
#define HH 8
#define DH 64
#define MT (BB*TT)   // 4096
#define NC 32
#define CS 64

// ---- scratch (static device globals; no allocation) ----
__device__ __half g_Xh[MT*DD];
__device__ __half g_W5h[5*DD*DD];
__device__ __half g_Yh[MT*DD];
__device__ __half g_Qh[MT*DD];
__device__ __half g_Kh[MT*DD];
__device__ __half g_Vh[MT*DD];
__device__ __half g_Gh[MT*DD];
__device__ __half g_B[BB*HH*NC*DH*DH];
__device__ __half g_S[BB*HH*NC*DH*DH];

// ---- helpers ----
__device__ __forceinline__ void mma16(float* c, const unsigned* a, const unsigned* b) {
    asm volatile("mma.sync.aligned.m16n8k16.row.col.f32.f16.f16.f32 "
        "{%0,%1,%2,%3}, {%4,%5,%6,%7}, {%8,%9}, {%0,%1,%2,%3};\n"
        : "+f"(c[0]), "+f"(c[1]), "+f"(c[2]), "+f"(c[3])
        : "r"(a[0]), "r"(a[1]), "r"(a[2]), "r"(a[3]), "r"(b[0]), "r"(b[1]));
}
__device__ __forceinline__ void ldm4(unsigned* r, unsigned addr) {
    asm volatile("ldmatrix.sync.aligned.m8n8.x4.shared.b16 {%0,%1,%2,%3}, [%4];"
        : "=r"(r[0]), "=r"(r[1]), "=r"(r[2]), "=r"(r[3]) : "r"(addr));
}
__device__ __forceinline__ void ldm4t(unsigned* r, unsigned addr) {
    asm volatile("ldmatrix.sync.aligned.m8n8.x4.trans.shared.b16 {%0,%1,%2,%3}, [%4];"
        : "=r"(r[0]), "=r"(r[1]), "=r"(r[2]), "=r"(r[3]) : "r"(addr));
}
__device__ __forceinline__ void cp16h(__half* smem, const __half* g) {
    unsigned s = (unsigned)__cvta_generic_to_shared(smem);
    asm volatile("cp.async.cg.shared.global [%0], [%1], 16;\n" :: "r"(s), "l"(g));
}
#define CP_COMMIT() asm volatile("cp.async.commit_group;\n" ::: "memory")
#define CP_WAIT1()  asm volatile("cp.async.wait_group 1;\n" ::: "memory")

// ============================================================
// fp16 pre-conversion: flat grid over x + 5 weights.
// ============================================================
__global__ __launch_bounds__(256) void conv_half(
    const float* __restrict__ x,
    const float* __restrict__ w0, const float* __restrict__ w1,
    const float* __restrict__ w2, const float* __restrict__ w3,
    const float* __restrict__ w4,
    __half* __restrict__ xo, __half* __restrict__ wo)
{
    int i = blockIdx.x * 256 + threadIdx.x;
    const float4* src;
    __half2* dst;
    int idx;
    if (i < 524288) {
        src = (const float4*)x; dst = (__half2*)xo; idx = i;
    } else {
        int j = i - 524288;
        int z = j >> 16;
        idx = j & 65535;
        const float* s = (z==0)?w0:(z==1)?w1:(z==2)?w2:(z==3)?w3:w4;
        src = (const float4*)s;
        dst = (__half2*)(wo + (size_t)z * DD * DD);
    }
    float4 v = src[idx];
    dst[2*idx]   = __floats2half2_rn(v.x, v.y);
    dst[2*idx+1] = __floats2half2_rn(v.z, v.w);
}

// ============================================================
// Projection GEMM: 256 threads, CTA 128x128, 8 warps (2M x 4N),
// warp tile 64x32, BK=64, 3-stage cp.async. fp16 out.
// ============================================================
#define SMP (3*(128*72 + 64*136)*2)   // 107520 bytes
#define SM2 (3*(64*40 + 32*136)*2)    // 41472 bytes

__device__ __forceinline__ void proj_body(const __half* __restrict__ A,
                                          const __half* __restrict__ B,
                                          __half* __restrict__ Ch,
                                          float alpha)
{
    constexpr int APAD = 72;
    constexpr int HASz = 128 * APAD;
    constexpr int HBSz = 64 * 136;

    extern __shared__ __half smh[];
    __half* Asm = smh;
    __half* Bsm = smh + 3*HASz;

    int tid = threadIdx.x;               // 0..255
    int w = tid >> 5, lane = tid & 31;
    int g = lane >> 2, t = lane & 3;
    int wm = (w >> 2) * 64;              // 0,64
    int wn = (w & 3) * 32;               // 0,32,64,96
    int bm = blockIdx.y * 128, bn = blockIdx.x * 128;

    int bkr = tid >> 2, bq = (tid & 3) * 32;   // B: row 0..63, 32-half seg
    const __half* Bg = B + (size_t)bkr * DD + bn + bq;

    float acc[4][4][4];
    #pragma unroll
    for (int i = 0; i < 4; i++)
        #pragma unroll
        for (int j = 0; j < 4; j++)
            #pragma unroll
            for (int q = 0; q < 4; q++) acc[i][j][q] = 0.f;

    auto load_chunk = [&](int kt, int s) {
        int off = kt * 64;
        // A: 128 rows x 64 halves = 1024 cp16 / 256 threads = 4
        #pragma unroll
        for (int i = 0; i < 4; i++) {
            int o = i * 256 + tid;
            int row = o >> 3, sg = (o & 7) * 8;
            cp16h(&Asm[s*HASz + row*APAD + sg],
                  A + (size_t)(bm + row) * DD + off + sg);
        }
        // B: 64 rows x 128 halves = 1024 cp16 / 256 threads = 4
        #pragma unroll
        for (int i = 0; i < 4; i++)
            cp16h(&Bsm[s*HBSz + bkr*136 + bq + 8*i], Bg + (size_t)off * DD + 8*i);
    };

    load_chunk(0, 0); CP_COMMIT();
    load_chunk(1, 1); CP_COMMIT();

    int lrow = lane & 15, lcol = (lane >> 4) << 3;

    #pragma unroll 1
    for (int kt = 0; kt < 8; kt++) {
        int cur = kt % 3;
        CP_WAIT1();
        __syncthreads();

        if (kt + 2 < 8)
            load_chunk(kt + 2, (kt + 2) % 3);
        CP_COMMIT();

        unsigned abase = (unsigned)__cvta_generic_to_shared(Asm + cur*HASz)
                       + ((wm + lrow) * APAD + lcol) * 2;
        unsigned bbase = (unsigned)__cvta_generic_to_shared(Bsm + cur*HBSz)
                       + (lrow * 136 + wn + lcol) * 2;

        #pragma unroll
        for (int ks = 0; ks < 4; ks++) {
            int k0 = ks * 16;
            unsigned a[4][4], bf[2][4];
            #pragma unroll
            for (int mt = 0; mt < 4; mt++)
                ldm4(a[mt], abase + (mt*16*APAD + k0) * 2);
            #pragma unroll
            for (int n2 = 0; n2 < 2; n2++)
                ldm4t(bf[n2], bbase + (k0*136 + n2*16) * 2);
            #pragma unroll
            for (int mt = 0; mt < 4; mt++)
                #pragma unroll
                for (int nt = 0; nt < 4; nt++)
                    mma16(acc[mt][nt], a[mt], &bf[nt >> 1][(nt & 1) * 2]);
        }
    }

    #pragma unroll
    for (int mt = 0; mt < 4; mt++)
        #pragma unroll
        for (int nt = 0; nt < 4; nt++) {
            int r = bm + wm + mt * 16 + g;
            int c = bn + wn + nt * 8 + 2 * t;
            ((__half2*)&Ch[(size_t)r * DD + c])[0] =
                __floats2half2_rn(alpha * acc[mt][nt][0], alpha * acc[mt][nt][1]);
            ((__half2*)&Ch[(size_t)(r + 8) * DD + c])[0] =
                __floats2half2_rn(alpha * acc[mt][nt][2], alpha * acc[mt][nt][3]);
        }
}

__global__ __launch_bounds__(256, 2) void proj_kv(const __half* __restrict__ x,
    const __half* __restrict__ W, __half* Ko, __half* Vo)
{
    const __half* Bp; __half* Cph;
    if (blockIdx.z == 0) { Bp = W + DD*DD;   Cph = Ko; }
    else                 { Bp = W + 2*DD*DD; Cph = Vo; }
    proj_body(x, Bp, Cph, 1.f);
}

__global__ __launch_bounds__(256, 2) void proj_qg(const __half* __restrict__ x,
    const __half* __restrict__ W, __half* Qo, __half* Go)
{
    const __half* Bp; __half* Cph; float alpha;
    if (blockIdx.z == 0) { Bp = W;           Cph = Qo; alpha = 0.125f; }
    else                 { Bp = W + 3*DD*DD; Cph = Go; alpha = 1.f; }
    proj_body(x, Bp, Cph, alpha);
}

// ============================================================
// Output GEMM: 128 threads, CTA 64x128, MTILES=2, BK=32, fp32 out.
// ============================================================
__global__ __launch_bounds__(128, 4) void gemm_out(const __half* __restrict__ A,
                                                   const __half* __restrict__ B,
                                                   float* __restrict__ C)
{
    constexpr int APAD = 40;
    constexpr int HASz = 64 * APAD;
    constexpr int HBSz = 32 * 136;

    extern __shared__ __half smh[];
    __half* Asm = smh;
    __half* Bsm = smh + 3*HASz;

    int tid = threadIdx.x;
    int w = tid >> 5, lane = tid & 31;
    int g = lane >> 2, t = lane & 3;
    int wm = (w >> 1) * 32;
    int wn = (w & 1) * 64;
    int bm = blockIdx.y * 64, bn = blockIdx.x * 128;

    int bkr = tid >> 2, bq = (tid & 3) * 32;
    const __half* Bg = B + (size_t)bkr * DD + bn + bq;

    float acc[2][8][4];
    #pragma unroll
    for (int i = 0; i < 2; i++)
        #pragma unroll
        for (int j = 0; j < 8; j++)
            #pragma unroll
            for (int q = 0; q < 4; q++) acc[i][j][q] = 0.f;

    auto load_chunk = [&](int kt, int s) {
        int off = kt * 32;
        #pragma unroll
        for (int i = 0; i < 2; i++) {
            int o = i * 128 + tid;
            int row = o >> 2, sg = (o & 3) * 8;
            cp16h(&Asm[s*HASz + row*APAD + sg],
                  A + (size_t)(bm + row) * DD + off + sg);
        }
        #pragma unroll
        for (int i = 0; i < 4; i++)
            cp16h(&Bsm[s*HBSz + bkr*136 + bq + 8*i], Bg + (size_t)off * DD + 8*i);
    };

    load_chunk(0, 0); CP_COMMIT();
    load_chunk(1, 1); CP_COMMIT();

    int lrow = lane & 15, lcol = (lane >> 4) << 3;

    #pragma unroll 1
    for (int kt = 0; kt < 16; kt++) {
        int cur = kt % 3;
        CP_WAIT1();
        __syncthreads();

        if (kt + 2 < 16)
            load_chunk(kt + 2, (kt + 2) % 3);
        CP_COMMIT();

        unsigned abase = (unsigned)__cvta_generic_to_shared(Asm + cur*HASz)
                       + ((wm + lrow) * APAD + lcol) * 2;
        unsigned bbase = (unsigned)__cvta_generic_to_shared(Bsm + cur*HBSz)
                       + (lrow * 136 + wn + lcol) * 2;

        #pragma unroll
        for (int ks = 0; ks < 2; ks++) {
            int k0 = ks * 16;
            unsigned a[2][4], bf[4][4];
            #pragma unroll
            for (int mt = 0; mt < 2; mt++)
                ldm4(a[mt], abase + (mt*16*APAD + k0) * 2);
            #pragma unroll
            for (int n2 = 0; n2 < 4; n2++)
                ldm4t(bf[n2], bbase + (k0*136 + n2*16) * 2);
            #pragma unroll
            for (int mt = 0; mt < 2; mt++)
                #pragma unroll
                for (int nt = 0; nt < 8; nt++)
                    mma16(acc[mt][nt], a[mt], &bf[nt >> 1][(nt & 1) * 2]);
        }
    }

    #pragma unroll
    for (int mt = 0; mt < 2; mt++)
        #pragma unroll
        for (int nt = 0; nt < 8; nt++) {
            int r = bm + wm + mt * 16 + g;
            int c = bn + wn + nt * 8 + 2 * t;
            *(float2*)&C[(size_t)r * DD + c] =
                make_float2(acc[mt][nt][0], acc[mt][nt][1]);
            *(float2*)&C[(size_t)(r + 8) * DD + c] =
                make_float2(acc[mt][nt][2], acc[mt][nt][3]);
        }
}

// ============================================================
// Chunkwise retention — fp16 mma path.
// ============================================================
#define TST 72

__global__ __launch_bounds__(256) void chunk_outer(const __half* __restrict__ K,
                                                   const __half* __restrict__ V,
                                                   __half* __restrict__ Bout)
{
    __shared__ __align__(16) __half Ksm[64*TST];
    __shared__ __align__(16) __half Vd[64*TST];

    int c = blockIdx.x, h = blockIdx.y, b = blockIdx.z;
    int tid = threadIdx.x;
    int w = tid >> 5, lane = tid & 31;
    int g = lane >> 2, t = lane & 3;
    int wi = (w >> 2) * 32, wj = (w & 3) * 16;

    float log2g = log2f(1.f - exp2f(-5.f - (float)h));

    int lr = tid >> 2, lc8 = (tid & 3) * 16;
    const __half* Kb = K + ((size_t)b * TT + (size_t)c * CS) * DD + h * DH;
    const __half* Vb = V + ((size_t)b * TT + (size_t)c * CS) * DD + h * DH;
    __half2 dec2 = __float2half2_rn(exp2f(log2g * (float)(CS - lr)));

    *(float4*)&Ksm[lr*TST + lc8]     = *(const float4*)&Kb[(size_t)lr * DD + lc8];
    *(float4*)&Ksm[lr*TST + lc8 + 8] = *(const float4*)&Kb[(size_t)lr * DD + lc8 + 8];
    #pragma unroll
    for (int u = 0; u < 8; u++) {
        __half2 v = *(const __half2*)&Vb[(size_t)lr * DD + lc8 + 2*u];
        *(__half2*)&Vd[lr*TST + lc8 + 2*u] = __hmul2(v, dec2);
    }
    __syncthreads();

    float bacc[2][2][4];
    #pragma unroll
    for (int i = 0; i < 2; i++)
        #pragma unroll
        for (int j = 0; j < 2; j++)
            #pragma unroll
            for (int q = 0; q < 4; q++) bacc[i][j][q] = 0.f;

    unsigned kbase = (unsigned)__cvta_generic_to_shared(Ksm);
    unsigned vbase = (unsigned)__cvta_generic_to_shared(Vd);
    int lrow = lane & 15, lcol = (lane >> 4) << 3;
    int jrow = (lane & 7) | ((lane >> 4) << 3);
    int dcol = ((lane >> 3) & 1) << 3;

    #pragma unroll
    for (int ks = 0; ks < 4; ks++) {
        int j0 = ks * 16;
        unsigned a[2][4], bv[4];
        #pragma unroll
        for (int mt = 0; mt < 2; mt++)
            ldm4t(a[mt], kbase + ((j0 + jrow)*TST + wi + mt*16 + dcol) * 2);
        ldm4t(bv, vbase + ((j0 + lrow)*TST + wj + lcol) * 2);
        #pragma unroll
        for (int mt = 0; mt < 2; mt++)
            #pragma unroll
            for (int nt = 0; nt < 2; nt++)
                mma16(bacc[mt][nt], a[mt], &bv[2*nt]);
    }

    size_t base = (((size_t)(b * HH + h)) * NC + c) * (DH * DH);
    #pragma unroll
    for (int mt = 0; mt < 2; mt++)
        #pragma unroll
        for (int nt = 0; nt < 2; nt++) {
            int r = wi + mt * 16 + g;
            int cc = wj + nt * 8 + 2 * t;
            *(__half2*)&Bout[base + r * DH + cc] =
                __floats2half2_rn(bacc[mt][nt][0], bacc[mt][nt][1]);
            *(__half2*)&Bout[base + (r + 8) * DH + cc] =
                __floats2half2_rn(bacc[mt][nt][2], bacc[mt][nt][3]);
        }
}

// ============================================================
// Two-level parallel scan over chunks (fp16 I/O, fp32 math).
// ============================================================
__global__ __launch_bounds__(256) void scan_state(const __half2* __restrict__ Bm,
                                                  __half2* __restrict__ Sm)
{
    __shared__ float2 P[4][64];

    int bh = blockIdx.x;
    int h = bh & 7;
    float log2g = log2f(1.f - exp2f(-5.f - (float)h));
    float gc = exp2f(64.f * log2g);
    float gc8 = exp2f(64.f * 8.f * log2g);

    int seg = threadIdx.x >> 6;
    int el  = threadIdx.x & 63;
    int e = blockIdx.y * 64 + el;
    size_t base = (size_t)bh * NC * 2048 + e;

    float2 v[8];
    #pragma unroll
    for (int j = 0; j < 8; j++)
        v[j] = __half22float2(Bm[base + (size_t)(seg * 8 + j) * 2048]);

    float2 p = make_float2(0.f, 0.f);
    #pragma unroll
    for (int j = 0; j < 8; j++) {
        p.x = gc * p.x + v[j].x;
        p.y = gc * p.y + v[j].y;
    }
    P[seg][el] = p;
    __syncthreads();

    float2 off = make_float2(0.f, 0.f);
    #pragma unroll
    for (int sp = 0; sp < 3; sp++)
        if (sp < seg) {
            float2 q = P[sp][el];
            off.x = gc8 * off.x + q.x;
            off.y = gc8 * off.y + q.y;
        }

    float2 st = off;
    #pragma unroll
    for (int j = 0; j < 8; j++) {
        Sm[base + (size_t)(seg * 8 + j) * 2048] = __floats2half2_rn(st.x, st.y);
        st.x = gc * st.x + v[j].x;
        st.y = gc * st.y + v[j].y;
    }
}

// ============================================================
// intra + inter + GroupNorm + SiLU gate, fp16 mma
// ============================================================
__global__ __launch_bounds__(256) void retention_chunk(
    const __half* __restrict__ Q, const __half* __restrict__ K,
    const __half* __restrict__ V, const __half* __restrict__ Sm,
    const __half* __restrict__ G, const float* __restrict__ gnw,
    const float* __restrict__ gnb, __half* __restrict__ Y)
{
    __shared__ __align__(16) char smb[46608];
    __half* Qh = (__half*)smb;
    __half* Kh = (__half*)(smb + 9216);
    __half* Vh = (__half*)(smb + 18432);
    __half* Th = (__half*)(smb + 27648);
    __half* Sh = (__half*)(smb + 36864);
    float* gp  = (float*)(smb + 46080);
    float* gn_ = (float*)(smb + 46340);
    float* Os  = (float*)smb;

    int c = blockIdx.x, h = blockIdx.y, b = blockIdx.z;
    int tid = threadIdx.x;
    int w = tid >> 5, lane = tid & 31;
    int g = lane >> 2, t = lane & 3;
    int wi = (w >> 2) * 32, wj = (w & 3) * 16;

    float log2g = log2f(1.f - exp2f(-5.f - (float)h));
    if (tid < 65) gp[tid] = exp2f(log2g * (float)tid);
    if (tid < 64) gn_[tid] = exp2f(log2g * (float)(tid - 64));

    int lr = tid >> 2, lc8 = (tid & 3) * 16;
    size_t rowbase = ((size_t)b * TT + (size_t)c * CS + lr) * DD + h * DH;
    const __half* Qb = Q + rowbase;
    const __half* Kb = K + rowbase;
    const __half* Vb = V + rowbase;
    const __half* Tb = Sm + (((size_t)(b * HH + h)) * NC + c) * (DH * DH);
    __half2 dec2 = __float2half2_rn(exp2f(log2g * (float)(CS - lr)));

    *(float4*)&Qh[lr*TST + lc8]     = *(const float4*)&Qb[lc8];
    *(float4*)&Qh[lr*TST + lc8 + 8] = *(const float4*)&Qb[lc8 + 8];
    *(float4*)&Kh[lr*TST + lc8]     = *(const float4*)&Kb[lc8];
    *(float4*)&Kh[lr*TST + lc8 + 8] = *(const float4*)&Kb[lc8 + 8];
    #pragma unroll
    for (int u = 0; u < 8; u++) {
        __half2 v = *(const __half2*)&Vb[lc8 + 2*u];
        *(__half2*)&Vh[lr*TST + lc8 + 2*u] = __hmul2(v, dec2);
    }
    *(float4*)&Th[lr*TST + lc8]     = *(const float4*)&Tb[lr * DH + lc8];
    *(float4*)&Th[lr*TST + lc8 + 8] = *(const float4*)&Tb[lr * DH + lc8 + 8];
    __syncthreads();

    unsigned qbase = (unsigned)__cvta_generic_to_shared(Qh);
    unsigned kbase = (unsigned)__cvta_generic_to_shared(Kh);
    unsigned vbase = (unsigned)__cvta_generic_to_shared(Vh);
    unsigned tbase = (unsigned)__cvta_generic_to_shared(Th);
    unsigned sbase2 = (unsigned)__cvta_generic_to_shared(Sh);
    int lrow = lane & 15, lcol = (lane >> 4) << 3;
    int nrow = (lane & 7) | ((lane >> 4) << 3);
    int kc = ((lane >> 3) & 1) << 3;

    float sacc[2][2][4], iacc[2][2][4];
    #pragma unroll
    for (int i = 0; i < 2; i++)
        #pragma unroll
        for (int j = 0; j < 2; j++)
            #pragma unroll
            for (int q = 0; q < 4; q++) { sacc[i][j][q] = 0.f; iacc[i][j][q] = 0.f; }

    #pragma unroll
    for (int ks = 0; ks < 4; ks++) {
        int k0 = ks * 16;
        unsigned a[2][4], bk[4], bt[4];
        #pragma unroll
        for (int mt = 0; mt < 2; mt++)
            ldm4(a[mt], qbase + ((wi + mt*16 + lrow)*TST + k0 + lcol) * 2);
        ldm4(bk, kbase + ((wj + nrow)*TST + k0 + kc) * 2);
        ldm4t(bt, tbase + ((k0 + lrow)*TST + wj + lcol) * 2);
        #pragma unroll
        for (int mt = 0; mt < 2; mt++)
            #pragma unroll
            for (int nt = 0; nt < 2; nt++) {
                mma16(sacc[mt][nt], a[mt], &bk[2*nt]);
                mma16(iacc[mt][nt], a[mt], &bt[2*nt]);
            }
    }

    #pragma unroll
    for (int mt = 0; mt < 2; mt++) {
        #pragma unroll
        for (int nt = 0; nt < 2; nt++) {
            int r0 = wi + mt * 16 + g;
            int c0 = wj + nt * 8 + 2 * t;
            float w0 = gn_[r0], w1 = gn_[r0 + 8];
            float m00 = (r0 >= c0) ? w0 : 0.f;
            float m01 = (r0 >= c0 + 1) ? w0 : 0.f;
            float m10 = (r0 + 8 >= c0) ? w1 : 0.f;
            float m11 = (r0 + 8 >= c0 + 1) ? w1 : 0.f;
            *(__half2*)&Sh[r0*TST + c0] =
                __floats2half2_rn(sacc[mt][nt][0]*m00, sacc[mt][nt][1]*m01);
            *(__half2*)&Sh[(r0+8)*TST + c0] =
                __floats2half2_rn(sacc[mt][nt][2]*m10, sacc[mt][nt][3]*m11);
        }
    }
    __syncthreads();

    float oacc[2][2][4];
    #pragma unroll
    for (int i = 0; i < 2; i++)
        #pragma unroll
        for (int j = 0; j < 2; j++)
            #pragma unroll
            for (int q = 0; q < 4; q++) oacc[i][j][q] = 0.f;

    #pragma unroll
    for (int ks = 0; ks < 4; ks++) {
        int k0 = ks * 16;
        unsigned a[2][4], bv[4];
        #pragma unroll
        for (int mt = 0; mt < 2; mt++)
            ldm4(a[mt], sbase2 + ((wi + mt*16 + lrow)*TST + k0 + lcol) * 2);
        ldm4t(bv, vbase + ((k0 + lrow)*TST + wj + lcol) * 2);
        #pragma unroll
        for (int mt = 0; mt < 2; mt++)
            #pragma unroll
            for (int nt = 0; nt < 2; nt++)
                mma16(oacc[mt][nt], a[mt], &bv[2*nt]);
    }

    #pragma unroll
    for (int mt = 0; mt < 2; mt++) {
        #pragma unroll
        for (int nt = 0; nt < 2; nt++) {
            int r0 = wi + mt * 16 + g;
            int c0 = wj + nt * 8 + 2 * t;
            float scA = gp[r0], scB = gp[r0 + 8];
            *(float2*)&Os[r0*68 + c0] = make_float2(
                oacc[mt][nt][0] + scA * iacc[mt][nt][0],
                oacc[mt][nt][1] + scA * iacc[mt][nt][1]);
            *(float2*)&Os[(r0+8)*68 + c0] = make_float2(
                oacc[mt][nt][2] + scB * iacc[mt][nt][2],
                oacc[mt][nt][3] + scB * iacc[mt][nt][3]);
        }
    }
    __syncthreads();

    int tok = tid >> 2, sub = tid & 3;
    float vals[16];
    float s = 0.f, sq = 0.f;
    #pragma unroll
    for (int u = 0; u < 16; u++) {
        float v = Os[tok * 68 + sub * 16 + u];
        vals[u] = v; s += v; sq += v * v;
    }
    s  += __shfl_xor_sync(0xffffffffu, s, 1);
    s  += __shfl_xor_sync(0xffffffffu, s, 2);
    sq += __shfl_xor_sync(0xffffffffu, sq, 1);
    sq += __shfl_xor_sync(0xffffffffu, sq, 2);
    float mean = s * (1.f / 64.f);
    float inv = rsqrtf(sq * (1.f / 64.f) - mean * mean + 1e-5f);

    size_t row = (size_t)b * TT + (size_t)c * CS + tok;
    int wcol = h * DH + sub * 16;
    const __half2* gh = (const __half2*)(G + row * DD + wcol);
    __half2* yp = (__half2*)(Y + row * DD + wcol);
    #pragma unroll
    for (int u4 = 0; u4 < 4; u4++) {
        float4 wv = *(const float4*)&gnw[wcol + u4 * 4];
        float4 bv = *(const float4*)&gnb[wcol + u4 * 4];
        float2 g0 = __half22float2(gh[u4*2]);
        float2 g1 = __half22float2(gh[u4*2+1]);
        float z0, z1, z2, z3;
        z0 = g0.x + (vals[u4*4+0] - mean) * inv * wv.x + bv.x; z0 = z0 / (1.f + expf(-z0));
        z1 = g0.y + (vals[u4*4+1] - mean) * inv * wv.y + bv.y; z1 = z1 / (1.f + expf(-z1));
        z2 = g1.x + (vals[u4*4+2] - mean) * inv * wv.z + bv.z; z2 = z2 / (1.f + expf(-z2));
        z3 = g1.y + (vals[u4*4+3] - mean) * inv * wv.w + bv.w; z3 = z3 / (1.f + expf(-z3));
        yp[u4*2]   = __floats2half2_rn(z0, z1);
        yp[u4*2+1] = __floats2half2_rn(z2, z3);
    }
}

// ============================================================
extern "C" void kernel_launch(void* const* d_in, const int* in_sizes, int n_in,
                              void* d_out, int out_size) {
    const float* x   = (const float*)d_in[0];
    const float* WQ  = (const float*)d_in[1];
    const float* WK  = (const float*)d_in[2];
    const float* WV  = (const float*)d_in[3];
    const float* WG  = (const float*)d_in[4];
    const float* WO  = (const float*)d_in[5];
    const float* gnw = (const float*)d_in[6];
    const float* gnb = (const float*)d_in[7];
    float* out = (float*)d_out;

    __half *Xh, *Wh, *Yh, *Qh, *Kh, *Vh, *Gh, *Bp, *Sp;
    cudaGetSymbolAddress((void**)&Xh, g_Xh);
    cudaGetSymbolAddress((void**)&Wh, g_W5h);
    cudaGetSymbolAddress((void**)&Yh, g_Yh);
    cudaGetSymbolAddress((void**)&Qh, g_Qh);
    cudaGetSymbolAddress((void**)&Kh, g_Kh);
    cudaGetSymbolAddress((void**)&Vh, g_Vh);
    cudaGetSymbolAddress((void**)&Gh, g_Gh);
    cudaGetSymbolAddress((void**)&Bp, g_B);
    cudaGetSymbolAddress((void**)&Sp, g_S);

    static cudaStream_t s1 = nullptr;
    static cudaEvent_t evFork = nullptr, evJoin = nullptr;
    if (!s1) {
        cudaStreamCreateWithFlags(&s1, cudaStreamNonBlocking);
        cudaEventCreateWithFlags(&evFork, cudaEventDisableTiming);
        cudaEventCreateWithFlags(&evJoin, cudaEventDisableTiming);
        cudaFuncSetAttribute(proj_kv,
                             cudaFuncAttributeMaxDynamicSharedMemorySize, SMP);
        cudaFuncSetAttribute(proj_qg,
                             cudaFuncAttributeMaxDynamicSharedMemorySize, SMP);
        cudaFuncSetAttribute(gemm_out,
                             cudaFuncAttributeMaxDynamicSharedMemorySize, SM2);
    }

    conv_half<<<3328, 256>>>(x, WQ, WK, WV, WG, WO, Xh, Wh);

    // fork: Q/G projection on side stream
    cudaEventRecord(evFork, 0);
    cudaStreamWaitEvent(s1, evFork, 0);
    proj_qg<<<dim3(DD / 128, MT / 128, 2), 256, SMP, s1>>>(Xh, Wh, Qh, Gh);

    // main stream: K/V projection -> chunk_outer -> scan
    proj_kv<<<dim3(DD / 128, MT / 128, 2), 256, SMP>>>(Xh, Wh, Kh, Vh);
    chunk_outer<<<dim3(NC, HH, BB), 256>>>(Kh, Vh, Bp);
    scan_state<<<dim3(BB * HH, 32), 256>>>((const __half2*)Bp, (__half2*)Sp);

    // join: retention needs Q, G from s1
    cudaEventRecord(evJoin, s1);
    cudaStreamWaitEvent(0, evJoin, 0);

    retention_chunk<<<dim3(NC, HH, BB), 256>>>(Qh, Kh, Vh, Sp,
                                               Gh, gnw, gnb, Yh);

    gemm_out<<<dim3(DD / 128, MT / 64), 128, SM2>>>(
        Yh, Wh + 4 * DD * DD, out);
}